// round 14
// baseline (speedup 1.0000x reference)
#include <cuda_runtime.h>
#include <cuda_fp16.h>
#include <math.h>

#define NN 100000
#define NE 1200000
#define NG 512
#define MAXD 64

// packed fp32x2 FMA (SASS FFMA2) — fp32 accuracy, 2x fma-pipe throughput
#define FMA2(acc, a, b) \
    asm("fma.rn.f32x2 %0, %1, %2, %0;" : "+l"(acc) : "l"(a), "l"(b))
#define PACKF2(out, lo, hi) \
    asm("mov.b64 %0, {%1, %2};" : "=l"(out) : "f"(lo), "f"(hi))
#define UNPACKF2(lo, hi, v) \
    asm("mov.b64 {%0, %1}, %2;" : "=f"(lo), "=f"(hi) : "l"(v))

// -------- scratch (device globals; no allocation) --------
static __device__ __half2 g_xh [NN * 32];   // fp16 x*ns (conv1 input)
static __device__ __half2 g_h1h[NN * 32];   // fp16 h1*ns (conv2 input)
static __device__ float   g_agg[NN * 64];   // gather output (fp32)
static __device__ float   g_h2 [NN * 64];   // conv2 output (fp32, for pooling)
static __device__ int     g_dego[NN];
static __device__ int     g_degi[NN];
static __device__ int     g_ebuf[NN * MAXD]; // fixed-stride dst buckets of src ids

// -------- init --------
__global__ void k_zero() {
    int i = blockIdx.x * blockDim.x + threadIdx.x;
    if (i < NN) { g_dego[i] = 0; g_degi[i] = 0; }
}

// -------- fused degrees + bucket fill (one edge pass) --------
__global__ void k_degfill(const int4* __restrict__ src4, const int4* __restrict__ dst4) {
    int i = blockIdx.x * blockDim.x + threadIdx.x;
    if (i < NE / 4) {
        int4 s = __ldg(&src4[i]);
        int4 d = __ldg(&dst4[i]);
        atomicAdd(&g_dego[s.x], 1); atomicAdd(&g_dego[s.y], 1);
        atomicAdd(&g_dego[s.z], 1); atomicAdd(&g_dego[s.w], 1);
        int p0 = atomicAdd(&g_degi[d.x], 1); g_ebuf[d.x * MAXD + p0] = s.x;
        int p1 = atomicAdd(&g_degi[d.y], 1); g_ebuf[d.y * MAXD + p1] = s.y;
        int p2 = atomicAdd(&g_degi[d.z], 1); g_ebuf[d.z * MAXD + p2] = s.z;
        int p3 = atomicAdd(&g_degi[d.w], 1); g_ebuf[d.w * MAXD + p3] = s.w;
    }
}

// -------- prep: g_xh = half(x * ns); ns computed from dego --------
__global__ void k_prep(const float* __restrict__ x) {
    int i = blockIdx.x * blockDim.x + threadIdx.x;   // over NN*16 float4s
    if (i < NN * 16) {
        float4 v = __ldg(&((const float4*)x)[i]);
        int dov = __ldg(&g_dego[i >> 4]); if (dov < 1) dov = 1;
        float s = rsqrtf((float)dov);
        g_xh[i * 2]     = __floats2half2_rn(v.x * s, v.y * s);
        g_xh[i * 2 + 1] = __floats2half2_rn(v.z * s, v.w * s);
    }
}

#define H2REF(x) (*reinterpret_cast<const __half2*>(&(x)))

// -------- gather: 1 warp/node; 2 edges per warp-LDG.64 (round-12 proven) --------
__global__ void __launch_bounds__(256) k_gather(const uint2* __restrict__ xin) {
    int gw = (blockIdx.x * blockDim.x + threadIdx.x) >> 5;
    if (gw >= NN) return;
    int lane = threadIdx.x & 31;
    int hf   = lane >> 4;    // 0 or 1
    int l16  = lane & 15;

    int deg = __ldg(&g_degi[gw]);
    const int* bucket = &g_ebuf[gw * MAXD];

    int sidx0 = __ldg(&bucket[lane]);
    int sidx1 = (deg > 32) ? __ldg(&bucket[32 + lane]) : 0;

    float ax0 = 0.f, ay0 = 0.f, ax1 = 0.f, ay1 = 0.f;
    #pragma unroll 1
    for (int e0 = 0; e0 < deg; e0 += 4) {
        int sv = (e0 < 32) ? sidx0 : sidx1;
        int sA = __shfl_sync(0xffffffffu, sv, e0 + hf);
        int sB = __shfl_sync(0xffffffffu, sv, e0 + 2 + hf);
        uint2 uA = (e0 + hf     < deg) ? __ldg(&xin[sA * 16 + l16]) : make_uint2(0u, 0u);
        uint2 uB = (e0 + 2 + hf < deg) ? __ldg(&xin[sB * 16 + l16]) : make_uint2(0u, 0u);
        __half2 t0 = __hadd2(H2REF(uA.x), H2REF(uB.x));
        __half2 t1 = __hadd2(H2REF(uA.y), H2REF(uB.y));
        float2 f0 = __half22float2(t0);
        float2 f1 = __half22float2(t1);
        ax0 += f0.x; ay0 += f0.y;
        ax1 += f1.x; ay1 += f1.y;
    }

    ax0 += __shfl_xor_sync(0xffffffffu, ax0, 16);
    ay0 += __shfl_xor_sync(0xffffffffu, ay0, 16);
    ax1 += __shfl_xor_sync(0xffffffffu, ax1, 16);
    ay1 += __shfl_xor_sync(0xffffffffu, ay1, 16);

    if (hf == 0) {
        int div_ = deg; if (div_ < 1) div_ = 1;
        float ndv = rsqrtf((float)div_);
        ((float4*)g_agg)[gw * 16 + l16] =
            make_float4(ax0 * ndv, ay0 * ndv, ax1 * ndv, ay1 * ndv);
    }
}

// -------- tiled GEMM with FFMA2 k-pair packing --------
// W stored transposed in smem (padded stride 68 floats) so the b-operand
// (w[k][c], w[k+1][c]) is a contiguous 64-bit register pair. acc holds
// (even-k sum, odd-k sum); folded with one add at the end. Pure fp32.
#define WT_S 68
__global__ void __launch_bounds__(256) k_gemm(
        int last,
        const float* __restrict__ W, const float* __restrict__ b,
        const float* __restrict__ gm, const float* __restrict__ bt) {
    __shared__ __align__(16) float Xs[64 * 64];
    __shared__ __align__(16) float Wt[64 * WT_S];

    int tid = threadIdx.x;
    int base = blockIdx.x * 64;

    const float4* agg4 = (const float4*)g_agg;
    const float4* W4 = (const float4*)W;
    #pragma unroll
    for (int i = 0; i < 4; i++) {
        int idx = tid + i * 256;            // over 1024 float4s
        int row = base + (idx >> 4);
        ((float4*)Xs)[idx] = (row < NN) ? __ldg(&agg4[row * 16 + (idx & 15)])
                                        : make_float4(0.f, 0.f, 0.f, 0.f);
        // transpose W into Wt: idx -> k = idx>>4, cols (idx&15)*4..+3
        float4 w = __ldg(&W4[idx]);
        int k  = idx >> 4;
        int c0 = (idx & 15) * 4;
        Wt[(c0 + 0) * WT_S + k] = w.x;
        Wt[(c0 + 1) * WT_S + k] = w.y;
        Wt[(c0 + 2) * WT_S + k] = w.z;
        Wt[(c0 + 3) * WT_S + k] = w.w;
    }
    __syncthreads();

    int R = tid >> 4;   // rows R*4..R*4+3
    int C = tid & 15;   // cols C*4..C*4+3

    // acc[r][c] packs (even-k partial, odd-k partial) for output (R*4+r, C*4+c)
    unsigned long long acc[4][4];
    {
        float4 bias = __ldg(&((const float4*)b)[C]);
        unsigned long long bi[4];
        PACKF2(bi[0], bias.x, 0.f);
        PACKF2(bi[1], bias.y, 0.f);
        PACKF2(bi[2], bias.z, 0.f);
        PACKF2(bi[3], bias.w, 0.f);
        #pragma unroll
        for (int r = 0; r < 4; r++) {
            acc[r][0] = bi[0]; acc[r][1] = bi[1];
            acc[r][2] = bi[2]; acc[r][3] = bi[3];
        }
    }

    const ulonglong2* Xv = reinterpret_cast<const ulonglong2*>(Xs);
    const ulonglong2* Wv = reinterpret_cast<const ulonglong2*>(Wt);

    #pragma unroll 4
    for (int k4 = 0; k4 < 16; k4++) {
        // a-pairs: (x[r][4k4], x[r][4k4+1]) and (+2,+3) — contiguous in Xs
        ulonglong2 a0 = Xv[(R * 4 + 0) * 16 + k4];
        ulonglong2 a1 = Xv[(R * 4 + 1) * 16 + k4];
        ulonglong2 a2 = Xv[(R * 4 + 2) * 16 + k4];
        ulonglong2 a3 = Xv[(R * 4 + 3) * 16 + k4];
        // b-pairs: (w[4k4][c], w[4k4+1][c]) and (+2,+3) — contiguous in Wt
        ulonglong2 w0 = Wv[(C * 4 + 0) * (WT_S / 4) + k4];
        ulonglong2 w1 = Wv[(C * 4 + 1) * (WT_S / 4) + k4];
        ulonglong2 w2 = Wv[(C * 4 + 2) * (WT_S / 4) + k4];
        ulonglong2 w3 = Wv[(C * 4 + 3) * (WT_S / 4) + k4];
        FMA2(acc[0][0], a0.x, w0.x); FMA2(acc[0][0], a0.y, w0.y);
        FMA2(acc[0][1], a0.x, w1.x); FMA2(acc[0][1], a0.y, w1.y);
        FMA2(acc[0][2], a0.x, w2.x); FMA2(acc[0][2], a0.y, w2.y);
        FMA2(acc[0][3], a0.x, w3.x); FMA2(acc[0][3], a0.y, w3.y);
        FMA2(acc[1][0], a1.x, w0.x); FMA2(acc[1][0], a1.y, w0.y);
        FMA2(acc[1][1], a1.x, w1.x); FMA2(acc[1][1], a1.y, w1.y);
        FMA2(acc[1][2], a1.x, w2.x); FMA2(acc[1][2], a1.y, w2.y);
        FMA2(acc[1][3], a1.x, w3.x); FMA2(acc[1][3], a1.y, w3.y);
        FMA2(acc[2][0], a2.x, w0.x); FMA2(acc[2][0], a2.y, w0.y);
        FMA2(acc[2][1], a2.x, w1.x); FMA2(acc[2][1], a2.y, w1.y);
        FMA2(acc[2][2], a2.x, w2.x); FMA2(acc[2][2], a2.y, w2.y);
        FMA2(acc[2][3], a2.x, w3.x); FMA2(acc[2][3], a2.y, w3.y);
        FMA2(acc[3][0], a3.x, w0.x); FMA2(acc[3][0], a3.y, w0.y);
        FMA2(acc[3][1], a3.x, w1.x); FMA2(acc[3][1], a3.y, w1.y);
        FMA2(acc[3][2], a3.x, w2.x); FMA2(acc[3][2], a3.y, w2.y);
        FMA2(acc[3][3], a3.x, w3.x); FMA2(acc[3][3], a3.y, w3.y);
    }

    float4 gmv = __ldg(&((const float4*)gm)[C]);
    float4 btv = __ldg(&((const float4*)bt)[C]);

    #pragma unroll
    for (int r = 0; r < 4; r++) {
        int row = base + R * 4 + r;
        float lo, hi;
        UNPACKF2(lo, hi, acc[r][0]); float o0 = lo + hi;
        UNPACKF2(lo, hi, acc[r][1]); float o1 = lo + hi;
        UNPACKF2(lo, hi, acc[r][2]); float o2 = lo + hi;
        UNPACKF2(lo, hi, acc[r][3]); float o3 = lo + hi;
        float s = o0 + o1 + o2 + o3;
        #pragma unroll
        for (int m = 1; m < 16; m <<= 1) s += __shfl_xor_sync(0xffffffffu, s, m);
        float mean = s * (1.f / 64.f);
        float d0 = o0 - mean, d1 = o1 - mean, d2 = o2 - mean, d3 = o3 - mean;
        float vv = d0 * d0 + d1 * d1 + d2 * d2 + d3 * d3;
        #pragma unroll
        for (int m = 1; m < 16; m <<= 1) vv += __shfl_xor_sync(0xffffffffu, vv, m);
        float inv = rsqrtf(vv * (1.f / 64.f) + 1e-5f);
        float y0 = fmaxf(d0 * inv * gmv.x + btv.x, 0.f);
        float y1 = fmaxf(d1 * inv * gmv.y + btv.y, 0.f);
        float y2 = fmaxf(d2 * inv * gmv.z + btv.z, 0.f);
        float y3 = fmaxf(d3 * inv * gmv.w + btv.w, 0.f);
        if (row < NN) {
            if (last) {
                ((float4*)g_h2)[row * 16 + C] = make_float4(y0, y1, y2, y3);
            } else {
                int dov = __ldg(&g_dego[row]); if (dov < 1) dov = 1;
                float nsr = rsqrtf((float)dov);
                g_h1h[row * 32 + C * 2]     = __floats2half2_rn(y0 * nsr, y1 * nsr);
                g_h1h[row * 32 + C * 2 + 1] = __floats2half2_rn(y2 * nsr, y3 * nsr);
            }
        }
    }
}

// -------- fused pooling + classifier head: one block (256 threads) per graph ----
__global__ void __launch_bounds__(256) k_poolcls(
        const int* __restrict__ gid,
        const float* __restrict__ Wc1, const float* __restrict__ bc1,
        const float* __restrict__ g3,  const float* __restrict__ be3,
        const float* __restrict__ Wc2, const float* __restrict__ bc2,
        const float* __restrict__ g4,  const float* __restrict__ be4,
        const float* __restrict__ Wc3, const float* __restrict__ bc3,
        float* __restrict__ out) {
    __shared__ float ss[256], mm[256];
    __shared__ float hA[64], hB[64], o1s[64], red[64];
    int g = blockIdx.x, t = threadIdx.x;
    int col = t & 63, chunk = t >> 6;

    int lo = 0, hi = NN;
    while (lo < hi) { int mid = (lo + hi) >> 1; if (__ldg(&gid[mid]) < g)     lo = mid + 1; else hi = mid; }
    int start = lo;
    lo = start; hi = NN;
    while (lo < hi) { int mid = (lo + hi) >> 1; if (__ldg(&gid[mid]) < g + 1) lo = mid + 1; else hi = mid; }
    int end = lo;

    float s = 0.f, m = 0.f;   // post-ReLU >= 0
    for (int n = start + chunk; n < end; n += 4) {
        float v = g_h2[n * 64 + col];
        s += v;
        m = fmaxf(m, v);
    }
    ss[t] = s; mm[t] = m;
    __syncthreads();

    float mv = 0.f, xv = 0.f;
    if (t < 64) {
        float cnt = (float)(end - start); if (cnt < 1.f) cnt = 1.f;
        mv = (ss[t] + ss[64 + t] + ss[128 + t] + ss[192 + t]) / cnt;
        xv = fmaxf(fmaxf(mm[t], mm[64 + t]), fmaxf(mm[128 + t], mm[192 + t]));
    }

    if (t < 64) red[t] = mv * mv;
    __syncthreads();
    for (int o = 32; o; o >>= 1) { if (t < o) red[t] += red[t + o]; __syncthreads(); }
    float nA = fmaxf(sqrtf(red[0]), 1e-12f); __syncthreads();
    if (t < 64) red[t] = xv * xv;
    __syncthreads();
    for (int o = 32; o; o >>= 1) { if (t < o) red[t] += red[t + o]; __syncthreads(); }
    float nB = fmaxf(sqrtf(red[0]), 1e-12f); __syncthreads();

    if (t < 64) { hA[t] = mv / nA; hB[t] = xv / nB; }
    __syncthreads();

    float acc = 0.f;
    if (t < 64) {
        acc = bc1[t];
        #pragma unroll 4
        for (int k = 0; k < 64; k++) acc += hA[k] * Wc1[k * 64 + t];
        #pragma unroll 4
        for (int k = 0; k < 64; k++) acc += hB[k] * Wc1[(64 + k) * 64 + t];
        red[t] = acc;
    }
    __syncthreads();
    for (int o = 32; o; o >>= 1) { if (t < o) red[t] += red[t + o]; __syncthreads(); }
    float mean = red[0] * (1.f / 64.f); __syncthreads();
    float dv = acc - mean;
    if (t < 64) red[t] = dv * dv;
    __syncthreads();
    for (int o = 32; o; o >>= 1) { if (t < o) red[t] += red[t + o]; __syncthreads(); }
    float inv = rsqrtf(red[0] * (1.f / 64.f) + 1e-5f); __syncthreads();
    if (t < 64) o1s[t] = fmaxf(dv * inv * g3[t] + be3[t], 0.f);
    __syncthreads();

    if (t < 64) {
        acc = bc2[t];
        #pragma unroll 4
        for (int k = 0; k < 64; k++) acc += o1s[k] * Wc2[k * 64 + t];
        red[t] = acc;
    }
    __syncthreads();
    for (int o = 32; o; o >>= 1) { if (t < o) red[t] += red[t + o]; __syncthreads(); }
    mean = red[0] * (1.f / 64.f); __syncthreads();
    dv = acc - mean;
    if (t < 64) red[t] = dv * dv;
    __syncthreads();
    for (int o = 32; o; o >>= 1) { if (t < o) red[t] += red[t + o]; __syncthreads(); }
    inv = rsqrtf(red[0] * (1.f / 64.f) + 1e-5f); __syncthreads();
    float o2 = fmaxf(dv * inv * g4[t < 64 ? t : 0] + be4[t < 64 ? t : 0], 0.f);

    if (t < 64) red[t] = o2 * Wc3[t];
    __syncthreads();
    for (int o = 32; o; o >>= 1) { if (t < o) red[t] += red[t + o]; __syncthreads(); }
    if (t == 0) out[g] = red[0] + bc3[0];
}

extern "C" void kernel_launch(void* const* d_in, const int* in_sizes, int n_in,
                              void* d_out, int out_size) {
    const float* h   = (const float*)d_in[0];
    const int*   src = (const int*)  d_in[1];
    const int*   dst = (const int*)  d_in[2];
    const int*   gid = (const int*)  d_in[3];
    const float* W1  = (const float*)d_in[4];
    const float* b1  = (const float*)d_in[5];
    const float* W2  = (const float*)d_in[6];
    const float* b2  = (const float*)d_in[7];
    const float* g1  = (const float*)d_in[8];
    const float* be1 = (const float*)d_in[9];
    const float* g2  = (const float*)d_in[10];
    const float* be2 = (const float*)d_in[11];
    const float* g3  = (const float*)d_in[12];
    const float* be3 = (const float*)d_in[13];
    const float* g4  = (const float*)d_in[14];
    const float* be4 = (const float*)d_in[15];
    const float* Wc1 = (const float*)d_in[16];
    const float* bc1 = (const float*)d_in[17];
    const float* Wc2 = (const float*)d_in[18];
    const float* bc2 = (const float*)d_in[19];
    const float* Wc3 = (const float*)d_in[20];
    const float* bc3 = (const float*)d_in[21];
    float* out = (float*)d_out;

    uint2* xh = nullptr; uint2* h1h = nullptr;
    cudaGetSymbolAddress((void**)&xh,  g_xh);
    cudaGetSymbolAddress((void**)&h1h, g_h1h);

    k_zero   <<<(NN + 255) / 256, 256>>>();
    k_degfill<<<(NE / 4 + 255) / 256, 256>>>((const int4*)src, (const int4*)dst);
    k_prep   <<<(NN * 16 + 255) / 256, 256>>>(h);

    k_gather<<<(NN * 32 + 255) / 256, 256>>>(xh);
    k_gemm  <<<(NN + 63) / 64, 256>>>(0, W1, b1, g1, be1);
    k_gather<<<(NN * 32 + 255) / 256, 256>>>(h1h);
    k_gemm  <<<(NN + 63) / 64, 256>>>(1, W2, b2, g2, be2);

    k_poolcls<<<NG, 256>>>(gid, Wc1, bc1, g3, be3, Wc2, bc2, g4, be4, Wc3, bc3, out);
}

// round 15
// speedup vs baseline: 1.7497x; 1.7497x over previous
#include <cuda_runtime.h>
#include <cuda_fp16.h>
#include <math.h>

#define NN 100000
#define NE 1200000
#define NG 512
#define MAXD 64

// -------- scratch (device globals; no allocation) --------
static __device__ __half2  g_xh  [NN * 32];  // fp16 x*ns (conv1 input)
static __device__ __half2  g_h1h [NN * 32];  // fp16 h1*ns (conv2 input)
static __device__ unsigned g_aggh[NN * 32];  // gather output (fp16 half2 pairs)
static __device__ float    g_h2  [NN * 64];  // conv2 output (fp32, for pooling)
static __device__ int      g_dego[NN];
static __device__ int      g_degi[NN];
static __device__ int      g_ebuf[NN * MAXD];

// -------- init --------
__global__ void k_zero() {
    int i = blockIdx.x * blockDim.x + threadIdx.x;
    if (i < NN) { g_dego[i] = 0; g_degi[i] = 0; }
}

// -------- fused degrees + bucket fill --------
__global__ void k_degfill(const int4* __restrict__ src4, const int4* __restrict__ dst4) {
    int i = blockIdx.x * blockDim.x + threadIdx.x;
    if (i < NE / 4) {
        int4 s = __ldg(&src4[i]);
        int4 d = __ldg(&dst4[i]);
        atomicAdd(&g_dego[s.x], 1); atomicAdd(&g_dego[s.y], 1);
        atomicAdd(&g_dego[s.z], 1); atomicAdd(&g_dego[s.w], 1);
        int p0 = atomicAdd(&g_degi[d.x], 1); g_ebuf[d.x * MAXD + p0] = s.x;
        int p1 = atomicAdd(&g_degi[d.y], 1); g_ebuf[d.y * MAXD + p1] = s.y;
        int p2 = atomicAdd(&g_degi[d.z], 1); g_ebuf[d.z * MAXD + p2] = s.z;
        int p3 = atomicAdd(&g_degi[d.w], 1); g_ebuf[d.w * MAXD + p3] = s.w;
    }
}

// -------- prep: g_xh = half(x * ns) --------
__global__ void k_prep(const float* __restrict__ x) {
    int i = blockIdx.x * blockDim.x + threadIdx.x;
    if (i < NN * 16) {
        float4 v = __ldg(&((const float4*)x)[i]);
        int dov = __ldg(&g_dego[i >> 4]); if (dov < 1) dov = 1;
        float s = rsqrtf((float)dov);
        g_xh[i * 2]     = __floats2half2_rn(v.x * s, v.y * s);
        g_xh[i * 2 + 1] = __floats2half2_rn(v.z * s, v.w * s);
    }
}

#define H2REF(x) (*reinterpret_cast<const __half2*>(&(x)))

// -------- gather (round-12 proven) — now stores fp16 agg --------
__global__ void __launch_bounds__(256) k_gather(const uint2* __restrict__ xin) {
    int gw = (blockIdx.x * blockDim.x + threadIdx.x) >> 5;
    if (gw >= NN) return;
    int lane = threadIdx.x & 31;
    int hf   = lane >> 4;
    int l16  = lane & 15;

    int deg = __ldg(&g_degi[gw]);
    const int* bucket = &g_ebuf[gw * MAXD];

    int sidx0 = __ldg(&bucket[lane]);
    int sidx1 = (deg > 32) ? __ldg(&bucket[32 + lane]) : 0;

    float ax0 = 0.f, ay0 = 0.f, ax1 = 0.f, ay1 = 0.f;
    #pragma unroll 1
    for (int e0 = 0; e0 < deg; e0 += 4) {
        int sv = (e0 < 32) ? sidx0 : sidx1;
        int sA = __shfl_sync(0xffffffffu, sv, e0 + hf);
        int sB = __shfl_sync(0xffffffffu, sv, e0 + 2 + hf);
        uint2 uA = (e0 + hf     < deg) ? __ldg(&xin[sA * 16 + l16]) : make_uint2(0u, 0u);
        uint2 uB = (e0 + 2 + hf < deg) ? __ldg(&xin[sB * 16 + l16]) : make_uint2(0u, 0u);
        __half2 t0 = __hadd2(H2REF(uA.x), H2REF(uB.x));
        __half2 t1 = __hadd2(H2REF(uA.y), H2REF(uB.y));
        float2 f0 = __half22float2(t0);
        float2 f1 = __half22float2(t1);
        ax0 += f0.x; ay0 += f0.y;
        ax1 += f1.x; ay1 += f1.y;
    }

    ax0 += __shfl_xor_sync(0xffffffffu, ax0, 16);
    ay0 += __shfl_xor_sync(0xffffffffu, ay0, 16);
    ax1 += __shfl_xor_sync(0xffffffffu, ax1, 16);
    ay1 += __shfl_xor_sync(0xffffffffu, ay1, 16);

    if (hf == 0) {
        int div_ = deg; if (div_ < 1) div_ = 1;
        float ndv = rsqrtf((float)div_);
        __half2 h0 = __floats2half2_rn(ax0 * ndv, ay0 * ndv);
        __half2 h1 = __floats2half2_rn(ax1 * ndv, ay1 * ndv);
        ((uint2*)g_aggh)[gw * 16 + l16] =
            make_uint2(*reinterpret_cast<unsigned*>(&h0), *reinterpret_cast<unsigned*>(&h1));
    }
}

// -------- tensor-core GEMM: mma.sync m16n8k16 fp16->fp32, fused LN/ReLU --------
// Block 128 threads = 4 warps; warp w handles rows base + w*16 .. +15.
#define XP 72   // smem row stride in halves (144B: 16B-aligned, conflict-free ldmatrix)

__device__ __forceinline__ void ldsm_x4(unsigned& r0, unsigned& r1, unsigned& r2, unsigned& r3, unsigned addr) {
    asm volatile("ldmatrix.sync.aligned.m8n8.x4.shared.b16 {%0,%1,%2,%3}, [%4];"
                 : "=r"(r0), "=r"(r1), "=r"(r2), "=r"(r3) : "r"(addr));
}
__device__ __forceinline__ void ldsm_x2t(unsigned& r0, unsigned& r1, unsigned addr) {
    asm volatile("ldmatrix.sync.aligned.m8n8.x2.trans.shared.b16 {%0,%1}, [%2];"
                 : "=r"(r0), "=r"(r1) : "r"(addr));
}
__device__ __forceinline__ void mma16816(float* c, const unsigned* a, const unsigned* bf) {
    asm volatile("mma.sync.aligned.m16n8k16.row.col.f32.f16.f16.f32 "
                 "{%0,%1,%2,%3},{%4,%5,%6,%7},{%8,%9},{%0,%1,%2,%3};"
                 : "+f"(c[0]), "+f"(c[1]), "+f"(c[2]), "+f"(c[3])
                 : "r"(a[0]), "r"(a[1]), "r"(a[2]), "r"(a[3]), "r"(bf[0]), "r"(bf[1]));
}

__global__ void __launch_bounds__(128) k_gemm(
        int last,
        const float* __restrict__ W, const float* __restrict__ b,
        const float* __restrict__ gm, const float* __restrict__ bt) {
    __shared__ __align__(16) __half Xh[64 * XP];
    __shared__ __align__(16) __half Wh[64 * XP];
    __shared__ float bs[64], gms[64], bts[64];

    int tid = threadIdx.x;
    int base = blockIdx.x * 64;

    // W fp32 -> fp16 smem (row-major, stride XP)
    const float4* W4 = (const float4*)W;
    #pragma unroll
    for (int i = 0; i < 8; i++) {
        int idx = tid + i * 128;            // 0..1023 float4s
        float4 w = __ldg(&W4[idx]);
        int k  = idx >> 4;
        int c0 = (idx & 15) * 4;
        __half2* dst = (__half2*)&Wh[k * XP + c0];
        dst[0] = __floats2half2_rn(w.x, w.y);
        dst[1] = __floats2half2_rn(w.z, w.w);
    }
    if (tid < 64) { bs[tid] = b[tid]; gms[tid] = gm[tid]; bts[tid] = bt[tid]; }

    // X tile fp16 smem
    const uint4* ag = (const uint4*)g_aggh;
    #pragma unroll
    for (int i = 0; i < 4; i++) {
        int idx = tid + i * 128;            // 0..511 uint4s
        int row = idx >> 3;
        int cu  = idx & 7;
        int grow = base + row;
        uint4 v = (grow < NN) ? __ldg(&ag[grow * 8 + cu]) : make_uint4(0u, 0u, 0u, 0u);
        *(uint4*)&Xh[row * XP + cu * 8] = v;
    }
    __syncthreads();

    int w    = tid >> 5;
    int lane = tid & 31;
    int g    = lane >> 2;
    int tig  = lane & 3;

    float c[8][4];
    #pragma unroll
    for (int nt = 0; nt < 8; nt++)
        #pragma unroll
        for (int j = 0; j < 4; j++) c[nt][j] = 0.f;

    unsigned xbase = (unsigned)__cvta_generic_to_shared(Xh);
    unsigned wbase = (unsigned)__cvta_generic_to_shared(Wh);

    #pragma unroll
    for (int ks = 0; ks < 4; ks++) {
        unsigned a[4];
        unsigned aaddr = xbase +
            (((w * 16 + (lane & 15)) * XP + ks * 16 + (lane >> 4) * 8) << 1);
        ldsm_x4(a[0], a[1], a[2], a[3], aaddr);
        #pragma unroll
        for (int nt = 0; nt < 8; nt++) {
            unsigned bf[2];
            unsigned baddr = wbase + (((ks * 16 + (lane & 15)) * XP + nt * 8) << 1);
            ldsm_x2t(bf[0], bf[1], baddr);
            mma16816(c[nt], a, bf);
        }
    }

    // bias
    #pragma unroll
    for (int nt = 0; nt < 8; nt++) {
        float b0 = bs[nt * 8 + 2 * tig];
        float b1 = bs[nt * 8 + 2 * tig + 1];
        c[nt][0] += b0; c[nt][1] += b1;
        c[nt][2] += b0; c[nt][3] += b1;
    }

    // LayerNorm rows g (regs 0,1) and g+8 (regs 2,3); 4 lanes/row -> 2 shfl reduce
    float sA = 0.f, sB = 0.f;
    #pragma unroll
    for (int nt = 0; nt < 8; nt++) { sA += c[nt][0] + c[nt][1]; sB += c[nt][2] + c[nt][3]; }
    sA += __shfl_xor_sync(0xffffffffu, sA, 1); sA += __shfl_xor_sync(0xffffffffu, sA, 2);
    sB += __shfl_xor_sync(0xffffffffu, sB, 1); sB += __shfl_xor_sync(0xffffffffu, sB, 2);
    float mA = sA * (1.f / 64.f), mB = sB * (1.f / 64.f);

    float vA = 0.f, vB = 0.f;
    #pragma unroll
    for (int nt = 0; nt < 8; nt++) {
        float d;
        d = c[nt][0] - mA; vA += d * d;
        d = c[nt][1] - mA; vA += d * d;
        d = c[nt][2] - mB; vB += d * d;
        d = c[nt][3] - mB; vB += d * d;
    }
    vA += __shfl_xor_sync(0xffffffffu, vA, 1); vA += __shfl_xor_sync(0xffffffffu, vA, 2);
    vB += __shfl_xor_sync(0xffffffffu, vB, 1); vB += __shfl_xor_sync(0xffffffffu, vB, 2);
    float iA = rsqrtf(vA * (1.f / 64.f) + 1e-5f);
    float iB = rsqrtf(vB * (1.f / 64.f) + 1e-5f);

    int rowA = base + w * 16 + g;
    int rowB = rowA + 8;

    if (last) {
        #pragma unroll
        for (int nt = 0; nt < 8; nt++) {
            int col = nt * 8 + 2 * tig;
            float gm0 = gms[col], gm1 = gms[col + 1];
            float bt0 = bts[col], bt1 = bts[col + 1];
            if (rowA < NN) {
                float y0 = fmaxf((c[nt][0] - mA) * iA * gm0 + bt0, 0.f);
                float y1 = fmaxf((c[nt][1] - mA) * iA * gm1 + bt1, 0.f);
                *(float2*)&g_h2[rowA * 64 + col] = make_float2(y0, y1);
            }
            if (rowB < NN) {
                float y2 = fmaxf((c[nt][2] - mB) * iB * gm0 + bt0, 0.f);
                float y3 = fmaxf((c[nt][3] - mB) * iB * gm1 + bt1, 0.f);
                *(float2*)&g_h2[rowB * 64 + col] = make_float2(y2, y3);
            }
        }
    } else {
        float nsA = 0.f, nsB = 0.f;
        if (rowA < NN) { int dv = __ldg(&g_dego[rowA]); if (dv < 1) dv = 1; nsA = rsqrtf((float)dv); }
        if (rowB < NN) { int dv = __ldg(&g_dego[rowB]); if (dv < 1) dv = 1; nsB = rsqrtf((float)dv); }
        #pragma unroll
        for (int nt = 0; nt < 8; nt++) {
            int col = nt * 8 + 2 * tig;
            float gm0 = gms[col], gm1 = gms[col + 1];
            float bt0 = bts[col], bt1 = bts[col + 1];
            if (rowA < NN) {
                float y0 = fmaxf((c[nt][0] - mA) * iA * gm0 + bt0, 0.f);
                float y1 = fmaxf((c[nt][1] - mA) * iA * gm1 + bt1, 0.f);
                g_h1h[rowA * 32 + nt * 4 + tig] = __floats2half2_rn(y0 * nsA, y1 * nsA);
            }
            if (rowB < NN) {
                float y2 = fmaxf((c[nt][2] - mB) * iB * gm0 + bt0, 0.f);
                float y3 = fmaxf((c[nt][3] - mB) * iB * gm1 + bt1, 0.f);
                g_h1h[rowB * 32 + nt * 4 + tig] = __floats2half2_rn(y2 * nsB, y3 * nsB);
            }
        }
    }
}

// -------- fused pooling + classifier head: one block (256 threads) per graph ----
__global__ void __launch_bounds__(256) k_poolcls(
        const int* __restrict__ gid,
        const float* __restrict__ Wc1, const float* __restrict__ bc1,
        const float* __restrict__ g3,  const float* __restrict__ be3,
        const float* __restrict__ Wc2, const float* __restrict__ bc2,
        const float* __restrict__ g4,  const float* __restrict__ be4,
        const float* __restrict__ Wc3, const float* __restrict__ bc3,
        float* __restrict__ out) {
    __shared__ float ss[256], mm[256];
    __shared__ float hA[64], hB[64], o1s[64], red[64];
    int g = blockIdx.x, t = threadIdx.x;
    int col = t & 63, chunk = t >> 6;

    int lo = 0, hi = NN;
    while (lo < hi) { int mid = (lo + hi) >> 1; if (__ldg(&gid[mid]) < g)     lo = mid + 1; else hi = mid; }
    int start = lo;
    lo = start; hi = NN;
    while (lo < hi) { int mid = (lo + hi) >> 1; if (__ldg(&gid[mid]) < g + 1) lo = mid + 1; else hi = mid; }
    int end = lo;

    float s = 0.f, m = 0.f;   // post-ReLU >= 0
    for (int n = start + chunk; n < end; n += 4) {
        float v = g_h2[n * 64 + col];
        s += v;
        m = fmaxf(m, v);
    }
    ss[t] = s; mm[t] = m;
    __syncthreads();

    float mv = 0.f, xv = 0.f;
    if (t < 64) {
        float cnt = (float)(end - start); if (cnt < 1.f) cnt = 1.f;
        mv = (ss[t] + ss[64 + t] + ss[128 + t] + ss[192 + t]) / cnt;
        xv = fmaxf(fmaxf(mm[t], mm[64 + t]), fmaxf(mm[128 + t], mm[192 + t]));
    }

    if (t < 64) red[t] = mv * mv;
    __syncthreads();
    for (int o = 32; o; o >>= 1) { if (t < o) red[t] += red[t + o]; __syncthreads(); }
    float nA = fmaxf(sqrtf(red[0]), 1e-12f); __syncthreads();
    if (t < 64) red[t] = xv * xv;
    __syncthreads();
    for (int o = 32; o; o >>= 1) { if (t < o) red[t] += red[t + o]; __syncthreads(); }
    float nB = fmaxf(sqrtf(red[0]), 1e-12f); __syncthreads();

    if (t < 64) { hA[t] = mv / nA; hB[t] = xv / nB; }
    __syncthreads();

    float acc = 0.f;
    if (t < 64) {
        acc = bc1[t];
        #pragma unroll 4
        for (int k = 0; k < 64; k++) acc += hA[k] * Wc1[k * 64 + t];
        #pragma unroll 4
        for (int k = 0; k < 64; k++) acc += hB[k] * Wc1[(64 + k) * 64 + t];
        red[t] = acc;
    }
    __syncthreads();
    for (int o = 32; o; o >>= 1) { if (t < o) red[t] += red[t + o]; __syncthreads(); }
    float mean = red[0] * (1.f / 64.f); __syncthreads();
    float dv = acc - mean;
    if (t < 64) red[t] = dv * dv;
    __syncthreads();
    for (int o = 32; o; o >>= 1) { if (t < o) red[t] += red[t + o]; __syncthreads(); }
    float inv = rsqrtf(red[0] * (1.f / 64.f) + 1e-5f); __syncthreads();
    if (t < 64) o1s[t] = fmaxf(dv * inv * g3[t] + be3[t], 0.f);
    __syncthreads();

    if (t < 64) {
        acc = bc2[t];
        #pragma unroll 4
        for (int k = 0; k < 64; k++) acc += o1s[k] * Wc2[k * 64 + t];
        red[t] = acc;
    }
    __syncthreads();
    for (int o = 32; o; o >>= 1) { if (t < o) red[t] += red[t + o]; __syncthreads(); }
    mean = red[0] * (1.f / 64.f); __syncthreads();
    dv = acc - mean;
    if (t < 64) red[t] = dv * dv;
    __syncthreads();
    for (int o = 32; o; o >>= 1) { if (t < o) red[t] += red[t + o]; __syncthreads(); }
    inv = rsqrtf(red[0] * (1.f / 64.f) + 1e-5f); __syncthreads();
    float o2 = fmaxf(dv * inv * g4[t < 64 ? t : 0] + be4[t < 64 ? t : 0], 0.f);

    if (t < 64) red[t] = o2 * Wc3[t];
    __syncthreads();
    for (int o = 32; o; o >>= 1) { if (t < o) red[t] += red[t + o]; __syncthreads(); }
    if (t == 0) out[g] = red[0] + bc3[0];
}

extern "C" void kernel_launch(void* const* d_in, const int* in_sizes, int n_in,
                              void* d_out, int out_size) {
    const float* h   = (const float*)d_in[0];
    const int*   src = (const int*)  d_in[1];
    const int*   dst = (const int*)  d_in[2];
    const int*   gid = (const int*)  d_in[3];
    const float* W1  = (const float*)d_in[4];
    const float* b1  = (const float*)d_in[5];
    const float* W2  = (const float*)d_in[6];
    const float* b2  = (const float*)d_in[7];
    const float* g1  = (const float*)d_in[8];
    const float* be1 = (const float*)d_in[9];
    const float* g2  = (const float*)d_in[10];
    const float* be2 = (const float*)d_in[11];
    const float* g3  = (const float*)d_in[12];
    const float* be3 = (const float*)d_in[13];
    const float* g4  = (const float*)d_in[14];
    const float* be4 = (const float*)d_in[15];
    const float* Wc1 = (const float*)d_in[16];
    const float* bc1 = (const float*)d_in[17];
    const float* Wc2 = (const float*)d_in[18];
    const float* bc2 = (const float*)d_in[19];
    const float* Wc3 = (const float*)d_in[20];
    const float* bc3 = (const float*)d_in[21];
    float* out = (float*)d_out;

    uint2* xh = nullptr; uint2* h1h = nullptr;
    cudaGetSymbolAddress((void**)&xh,  g_xh);
    cudaGetSymbolAddress((void**)&h1h, g_h1h);

    k_zero   <<<(NN + 255) / 256, 256>>>();
    k_degfill<<<(NE / 4 + 255) / 256, 256>>>((const int4*)src, (const int4*)dst);
    k_prep   <<<(NN * 16 + 255) / 256, 256>>>(h);

    k_gather<<<(NN * 32 + 255) / 256, 256>>>(xh);
    k_gemm  <<<(NN + 63) / 64, 128>>>(0, W1, b1, g1, be1);
    k_gather<<<(NN * 32 + 255) / 256, 256>>>(h1h);
    k_gemm  <<<(NN + 63) / 64, 128>>>(1, W2, b2, g2, be2);

    k_poolcls<<<NG, 256>>>(gid, Wc1, bc1, g3, be3, Wc2, bc2, g4, be4, Wc3, bc3, out);
}

// round 16
// speedup vs baseline: 1.7975x; 1.0274x over previous
#include <cuda_runtime.h>
#include <cuda_fp16.h>
#include <math.h>

#define NN 100000
#define NE 1200000
#define NG 512
#define MAXD 64

// -------- scratch (device globals; no allocation) --------
// feature arrays have NN+1 rows: row NN is an all-zero dummy for padded edges
static __device__ __half2  g_xh  [(NN + 1) * 32];
static __device__ __half2  g_h1h [(NN + 1) * 32];
static __device__ unsigned g_aggh[NN * 32];  // gather output (fp16 half2 pairs)
static __device__ float    g_h2  [NN * 64];  // conv2 output (fp32, for pooling)
static __device__ int      g_dego[NN];
static __device__ int      g_degi[NN];
static __device__ int      g_ebuf[NN * MAXD];

// -------- init: zero degrees + dummy rows --------
__global__ void k_zero() {
    int i = blockIdx.x * blockDim.x + threadIdx.x;
    if (i < NN) { g_dego[i] = 0; g_degi[i] = 0; }
    if (i < 32) {
        g_xh [NN * 32 + i] = __floats2half2_rn(0.f, 0.f);
        g_h1h[NN * 32 + i] = __floats2half2_rn(0.f, 0.f);
    }
}

// -------- fused degrees + bucket fill --------
__global__ void k_degfill(const int4* __restrict__ src4, const int4* __restrict__ dst4) {
    int i = blockIdx.x * blockDim.x + threadIdx.x;
    if (i < NE / 4) {
        int4 s = __ldg(&src4[i]);
        int4 d = __ldg(&dst4[i]);
        atomicAdd(&g_dego[s.x], 1); atomicAdd(&g_dego[s.y], 1);
        atomicAdd(&g_dego[s.z], 1); atomicAdd(&g_dego[s.w], 1);
        int p0 = atomicAdd(&g_degi[d.x], 1); g_ebuf[d.x * MAXD + p0] = s.x;
        int p1 = atomicAdd(&g_degi[d.y], 1); g_ebuf[d.y * MAXD + p1] = s.y;
        int p2 = atomicAdd(&g_degi[d.z], 1); g_ebuf[d.z * MAXD + p2] = s.z;
        int p3 = atomicAdd(&g_degi[d.w], 1); g_ebuf[d.w * MAXD + p3] = s.w;
    }
}

// -------- prep: g_xh = half(x * ns); pad buckets to ceil8(deg) with dummy NN --------
__global__ void k_prep(const float* __restrict__ x) {
    int i = blockIdx.x * blockDim.x + threadIdx.x;
    if (i < NN * 16) {
        float4 v = __ldg(&((const float4*)x)[i]);
        int dov = __ldg(&g_dego[i >> 4]); if (dov < 1) dov = 1;
        float s = rsqrtf((float)dov);
        g_xh[i * 2]     = __floats2half2_rn(v.x * s, v.y * s);
        g_xh[i * 2 + 1] = __floats2half2_rn(v.z * s, v.w * s);
    }
    if (i < NN) {
        int deg = __ldg(&g_degi[i]);
        int padded = (deg + 7) & ~7;
        for (int e = deg; e < padded; e++) g_ebuf[i * MAXD + e] = NN;
    }
}

#define H2REF(x) (*reinterpret_cast<const __half2*>(&(x)))

// -------- gather: 1 warp/node; 8-edge chunks, fully UNPREDICATED loads --------
// Half-warp h owns edges e0+h, e0+2+h, e0+4+h, e0+6+h. Padded bucket entries
// point at the all-zero dummy row NN (L1-hot), so no bounds checks anywhere.
__global__ void __launch_bounds__(256) k_gather(const uint2* __restrict__ xin) {
    int gw = (blockIdx.x * blockDim.x + threadIdx.x) >> 5;
    if (gw >= NN) return;
    int lane = threadIdx.x & 31;
    int hf   = lane >> 4;
    int l16  = lane & 15;

    int deg = __ldg(&g_degi[gw]);
    const int* bucket = &g_ebuf[gw * MAXD];

    int sidx0 = __ldg(&bucket[lane]);
    int sidx1 = __ldg(&bucket[32 + lane]);

    float ax0 = 0.f, ay0 = 0.f, ax1 = 0.f, ay1 = 0.f;
    #pragma unroll 1
    for (int e0 = 0; e0 < deg; e0 += 8) {
        int sv = (e0 < 32) ? sidx0 : sidx1;             // chunks are 8-aligned: no straddle
        int sA = __shfl_sync(0xffffffffu, sv, e0 + hf);       // srcLane wraps mod 32
        int sB = __shfl_sync(0xffffffffu, sv, e0 + 2 + hf);
        int sC = __shfl_sync(0xffffffffu, sv, e0 + 4 + hf);
        int sD = __shfl_sync(0xffffffffu, sv, e0 + 6 + hf);
        uint2 uA = __ldg(&xin[sA * 16 + l16]);
        uint2 uB = __ldg(&xin[sB * 16 + l16]);
        uint2 uC = __ldg(&xin[sC * 16 + l16]);
        uint2 uD = __ldg(&xin[sD * 16 + l16]);
        __half2 t0 = __hadd2(__hadd2(H2REF(uA.x), H2REF(uB.x)),
                             __hadd2(H2REF(uC.x), H2REF(uD.x)));
        __half2 t1 = __hadd2(__hadd2(H2REF(uA.y), H2REF(uB.y)),
                             __hadd2(H2REF(uC.y), H2REF(uD.y)));
        float2 f0 = __half22float2(t0);
        float2 f1 = __half22float2(t1);
        ax0 += f0.x; ay0 += f0.y;
        ax1 += f1.x; ay1 += f1.y;
    }

    ax0 += __shfl_xor_sync(0xffffffffu, ax0, 16);
    ay0 += __shfl_xor_sync(0xffffffffu, ay0, 16);
    ax1 += __shfl_xor_sync(0xffffffffu, ax1, 16);
    ay1 += __shfl_xor_sync(0xffffffffu, ay1, 16);

    if (hf == 0) {
        int div_ = deg; if (div_ < 1) div_ = 1;
        float ndv = rsqrtf((float)div_);
        __half2 h0 = __floats2half2_rn(ax0 * ndv, ay0 * ndv);
        __half2 h1 = __floats2half2_rn(ax1 * ndv, ay1 * ndv);
        ((uint2*)g_aggh)[gw * 16 + l16] =
            make_uint2(*reinterpret_cast<unsigned*>(&h0), *reinterpret_cast<unsigned*>(&h1));
    }
}

// -------- tensor-core GEMM (round-15 proven): mma m16n8k16, fused LN/ReLU --------
#define XP 72

__device__ __forceinline__ void ldsm_x4(unsigned& r0, unsigned& r1, unsigned& r2, unsigned& r3, unsigned addr) {
    asm volatile("ldmatrix.sync.aligned.m8n8.x4.shared.b16 {%0,%1,%2,%3}, [%4];"
                 : "=r"(r0), "=r"(r1), "=r"(r2), "=r"(r3) : "r"(addr));
}
__device__ __forceinline__ void ldsm_x2t(unsigned& r0, unsigned& r1, unsigned addr) {
    asm volatile("ldmatrix.sync.aligned.m8n8.x2.trans.shared.b16 {%0,%1}, [%2];"
                 : "=r"(r0), "=r"(r1) : "r"(addr));
}
__device__ __forceinline__ void mma16816(float* c, const unsigned* a, const unsigned* bf) {
    asm volatile("mma.sync.aligned.m16n8k16.row.col.f32.f16.f16.f32 "
                 "{%0,%1,%2,%3},{%4,%5,%6,%7},{%8,%9},{%0,%1,%2,%3};"
                 : "+f"(c[0]), "+f"(c[1]), "+f"(c[2]), "+f"(c[3])
                 : "r"(a[0]), "r"(a[1]), "r"(a[2]), "r"(a[3]), "r"(bf[0]), "r"(bf[1]));
}

__global__ void __launch_bounds__(128) k_gemm(
        int last,
        const float* __restrict__ W, const float* __restrict__ b,
        const float* __restrict__ gm, const float* __restrict__ bt) {
    __shared__ __align__(16) __half Xh[64 * XP];
    __shared__ __align__(16) __half Wh[64 * XP];
    __shared__ float bs[64], gms[64], bts[64];

    int tid = threadIdx.x;
    int base = blockIdx.x * 64;

    const float4* W4 = (const float4*)W;
    #pragma unroll
    for (int i = 0; i < 8; i++) {
        int idx = tid + i * 128;
        float4 w = __ldg(&W4[idx]);
        int k  = idx >> 4;
        int c0 = (idx & 15) * 4;
        __half2* dst = (__half2*)&Wh[k * XP + c0];
        dst[0] = __floats2half2_rn(w.x, w.y);
        dst[1] = __floats2half2_rn(w.z, w.w);
    }
    if (tid < 64) { bs[tid] = b[tid]; gms[tid] = gm[tid]; bts[tid] = bt[tid]; }

    const uint4* ag = (const uint4*)g_aggh;
    #pragma unroll
    for (int i = 0; i < 4; i++) {
        int idx = tid + i * 128;
        int row = idx >> 3;
        int cu  = idx & 7;
        int grow = base + row;
        uint4 v = (grow < NN) ? __ldg(&ag[grow * 8 + cu]) : make_uint4(0u, 0u, 0u, 0u);
        *(uint4*)&Xh[row * XP + cu * 8] = v;
    }
    __syncthreads();

    int w    = tid >> 5;
    int lane = tid & 31;
    int g    = lane >> 2;
    int tig  = lane & 3;

    float c[8][4];
    #pragma unroll
    for (int nt = 0; nt < 8; nt++)
        #pragma unroll
        for (int j = 0; j < 4; j++) c[nt][j] = 0.f;

    unsigned xbase = (unsigned)__cvta_generic_to_shared(Xh);
    unsigned wbase = (unsigned)__cvta_generic_to_shared(Wh);

    #pragma unroll
    for (int ks = 0; ks < 4; ks++) {
        unsigned a[4];
        unsigned aaddr = xbase +
            (((w * 16 + (lane & 15)) * XP + ks * 16 + (lane >> 4) * 8) << 1);
        ldsm_x4(a[0], a[1], a[2], a[3], aaddr);
        #pragma unroll
        for (int nt = 0; nt < 8; nt++) {
            unsigned bf[2];
            unsigned baddr = wbase + (((ks * 16 + (lane & 15)) * XP + nt * 8) << 1);
            ldsm_x2t(bf[0], bf[1], baddr);
            mma16816(c[nt], a, bf);
        }
    }

    #pragma unroll
    for (int nt = 0; nt < 8; nt++) {
        float b0 = bs[nt * 8 + 2 * tig];
        float b1 = bs[nt * 8 + 2 * tig + 1];
        c[nt][0] += b0; c[nt][1] += b1;
        c[nt][2] += b0; c[nt][3] += b1;
    }

    float sA = 0.f, sB = 0.f;
    #pragma unroll
    for (int nt = 0; nt < 8; nt++) { sA += c[nt][0] + c[nt][1]; sB += c[nt][2] + c[nt][3]; }
    sA += __shfl_xor_sync(0xffffffffu, sA, 1); sA += __shfl_xor_sync(0xffffffffu, sA, 2);
    sB += __shfl_xor_sync(0xffffffffu, sB, 1); sB += __shfl_xor_sync(0xffffffffu, sB, 2);
    float mA = sA * (1.f / 64.f), mB = sB * (1.f / 64.f);

    float vA = 0.f, vB = 0.f;
    #pragma unroll
    for (int nt = 0; nt < 8; nt++) {
        float d;
        d = c[nt][0] - mA; vA += d * d;
        d = c[nt][1] - mA; vA += d * d;
        d = c[nt][2] - mB; vB += d * d;
        d = c[nt][3] - mB; vB += d * d;
    }
    vA += __shfl_xor_sync(0xffffffffu, vA, 1); vA += __shfl_xor_sync(0xffffffffu, vA, 2);
    vB += __shfl_xor_sync(0xffffffffu, vB, 1); vB += __shfl_xor_sync(0xffffffffu, vB, 2);
    float iA = rsqrtf(vA * (1.f / 64.f) + 1e-5f);
    float iB = rsqrtf(vB * (1.f / 64.f) + 1e-5f);

    int rowA = base + w * 16 + g;
    int rowB = rowA + 8;

    if (last) {
        #pragma unroll
        for (int nt = 0; nt < 8; nt++) {
            int col = nt * 8 + 2 * tig;
            float gm0 = gms[col], gm1 = gms[col + 1];
            float bt0 = bts[col], bt1 = bts[col + 1];
            if (rowA < NN) {
                float y0 = fmaxf((c[nt][0] - mA) * iA * gm0 + bt0, 0.f);
                float y1 = fmaxf((c[nt][1] - mA) * iA * gm1 + bt1, 0.f);
                *(float2*)&g_h2[rowA * 64 + col] = make_float2(y0, y1);
            }
            if (rowB < NN) {
                float y2 = fmaxf((c[nt][2] - mB) * iB * gm0 + bt0, 0.f);
                float y3 = fmaxf((c[nt][3] - mB) * iB * gm1 + bt1, 0.f);
                *(float2*)&g_h2[rowB * 64 + col] = make_float2(y2, y3);
            }
        }
    } else {
        float nsA = 0.f, nsB = 0.f;
        if (rowA < NN) { int dv = __ldg(&g_dego[rowA]); if (dv < 1) dv = 1; nsA = rsqrtf((float)dv); }
        if (rowB < NN) { int dv = __ldg(&g_dego[rowB]); if (dv < 1) dv = 1; nsB = rsqrtf((float)dv); }
        #pragma unroll
        for (int nt = 0; nt < 8; nt++) {
            int col = nt * 8 + 2 * tig;
            float gm0 = gms[col], gm1 = gms[col + 1];
            float bt0 = bts[col], bt1 = bts[col + 1];
            if (rowA < NN) {
                float y0 = fmaxf((c[nt][0] - mA) * iA * gm0 + bt0, 0.f);
                float y1 = fmaxf((c[nt][1] - mA) * iA * gm1 + bt1, 0.f);
                g_h1h[rowA * 32 + nt * 4 + tig] = __floats2half2_rn(y0 * nsA, y1 * nsA);
            }
            if (rowB < NN) {
                float y2 = fmaxf((c[nt][2] - mB) * iB * gm0 + bt0, 0.f);
                float y3 = fmaxf((c[nt][3] - mB) * iB * gm1 + bt1, 0.f);
                g_h1h[rowB * 32 + nt * 4 + tig] = __floats2half2_rn(y2 * nsB, y3 * nsB);
            }
        }
    }
}

// -------- fused pooling + classifier head: 512 threads/graph (8-way scan) --------
__global__ void __launch_bounds__(512) k_poolcls(
        const int* __restrict__ gid,
        const float* __restrict__ Wc1, const float* __restrict__ bc1,
        const float* __restrict__ g3,  const float* __restrict__ be3,
        const float* __restrict__ Wc2, const float* __restrict__ bc2,
        const float* __restrict__ g4,  const float* __restrict__ be4,
        const float* __restrict__ Wc3, const float* __restrict__ bc3,
        float* __restrict__ out) {
    __shared__ float ss[512], mm[512];
    __shared__ float hA[64], hB[64], o1s[64], red[64];
    int g = blockIdx.x, t = threadIdx.x;
    int col = t & 63, chunk = t >> 6;   // 8 chunks

    int lo = 0, hi = NN;
    while (lo < hi) { int mid = (lo + hi) >> 1; if (__ldg(&gid[mid]) < g)     lo = mid + 1; else hi = mid; }
    int start = lo;
    lo = start; hi = NN;
    while (lo < hi) { int mid = (lo + hi) >> 1; if (__ldg(&gid[mid]) < g + 1) lo = mid + 1; else hi = mid; }
    int end = lo;

    float s = 0.f, m = 0.f;   // post-ReLU >= 0
    for (int n = start + chunk; n < end; n += 8) {
        float v = g_h2[n * 64 + col];
        s += v;
        m = fmaxf(m, v);
    }
    ss[t] = s; mm[t] = m;
    __syncthreads();

    float mv = 0.f, xv = 0.f;
    if (t < 64) {
        float cnt = (float)(end - start); if (cnt < 1.f) cnt = 1.f;
        float su = 0.f, mx = 0.f;
        #pragma unroll
        for (int c8 = 0; c8 < 8; c8++) {
            su += ss[c8 * 64 + t];
            mx = fmaxf(mx, mm[c8 * 64 + t]);
        }
        mv = su / cnt;
        xv = mx;
    }

    if (t < 64) red[t] = mv * mv;
    __syncthreads();
    for (int o = 32; o; o >>= 1) { if (t < o) red[t] += red[t + o]; __syncthreads(); }
    float nA = fmaxf(sqrtf(red[0]), 1e-12f); __syncthreads();
    if (t < 64) red[t] = xv * xv;
    __syncthreads();
    for (int o = 32; o; o >>= 1) { if (t < o) red[t] += red[t + o]; __syncthreads(); }
    float nB = fmaxf(sqrtf(red[0]), 1e-12f); __syncthreads();

    if (t < 64) { hA[t] = mv / nA; hB[t] = xv / nB; }
    __syncthreads();

    float acc = 0.f;
    if (t < 64) {
        acc = bc1[t];
        #pragma unroll 4
        for (int k = 0; k < 64; k++) acc += hA[k] * Wc1[k * 64 + t];
        #pragma unroll 4
        for (int k = 0; k < 64; k++) acc += hB[k] * Wc1[(64 + k) * 64 + t];
        red[t] = acc;
    }
    __syncthreads();
    for (int o = 32; o; o >>= 1) { if (t < o) red[t] += red[t + o]; __syncthreads(); }
    float mean = red[0] * (1.f / 64.f); __syncthreads();
    float dv = acc - mean;
    if (t < 64) red[t] = dv * dv;
    __syncthreads();
    for (int o = 32; o; o >>= 1) { if (t < o) red[t] += red[t + o]; __syncthreads(); }
    float inv = rsqrtf(red[0] * (1.f / 64.f) + 1e-5f); __syncthreads();
    if (t < 64) o1s[t] = fmaxf(dv * inv * g3[t] + be3[t], 0.f);
    __syncthreads();

    if (t < 64) {
        acc = bc2[t];
        #pragma unroll 4
        for (int k = 0; k < 64; k++) acc += o1s[k] * Wc2[k * 64 + t];
        red[t] = acc;
    }
    __syncthreads();
    for (int o = 32; o; o >>= 1) { if (t < o) red[t] += red[t + o]; __syncthreads(); }
    mean = red[0] * (1.f / 64.f); __syncthreads();
    dv = acc - mean;
    if (t < 64) red[t] = dv * dv;
    __syncthreads();
    for (int o = 32; o; o >>= 1) { if (t < o) red[t] += red[t + o]; __syncthreads(); }
    inv = rsqrtf(red[0] * (1.f / 64.f) + 1e-5f); __syncthreads();
    float o2 = fmaxf(dv * inv * g4[t < 64 ? t : 0] + be4[t < 64 ? t : 0], 0.f);

    if (t < 64) red[t] = o2 * Wc3[t];
    __syncthreads();
    for (int o = 32; o; o >>= 1) { if (t < o) red[t] += red[t + o]; __syncthreads(); }
    if (t == 0) out[g] = red[0] + bc3[0];
}

extern "C" void kernel_launch(void* const* d_in, const int* in_sizes, int n_in,
                              void* d_out, int out_size) {
    const float* h   = (const float*)d_in[0];
    const int*   src = (const int*)  d_in[1];
    const int*   dst = (const int*)  d_in[2];
    const int*   gid = (const int*)  d_in[3];
    const float* W1  = (const float*)d_in[4];
    const float* b1  = (const float*)d_in[5];
    const float* W2  = (const float*)d_in[6];
    const float* b2  = (const float*)d_in[7];
    const float* g1  = (const float*)d_in[8];
    const float* be1 = (const float*)d_in[9];
    const float* g2  = (const float*)d_in[10];
    const float* be2 = (const float*)d_in[11];
    const float* g3  = (const float*)d_in[12];
    const float* be3 = (const float*)d_in[13];
    const float* g4  = (const float*)d_in[14];
    const float* be4 = (const float*)d_in[15];
    const float* Wc1 = (const float*)d_in[16];
    const float* bc1 = (const float*)d_in[17];
    const float* Wc2 = (const float*)d_in[18];
    const float* bc2 = (const float*)d_in[19];
    const float* Wc3 = (const float*)d_in[20];
    const float* bc3 = (const float*)d_in[21];
    float* out = (float*)d_out;

    uint2* xh = nullptr; uint2* h1h = nullptr;
    cudaGetSymbolAddress((void**)&xh,  g_xh);
    cudaGetSymbolAddress((void**)&h1h, g_h1h);

    k_zero   <<<(NN + 255) / 256, 256>>>();
    k_degfill<<<(NE / 4 + 255) / 256, 256>>>((const int4*)src, (const int4*)dst);
    k_prep   <<<(NN * 16 + 255) / 256, 256>>>(h);

    k_gather<<<(NN * 32 + 255) / 256, 256>>>(xh);
    k_gemm  <<<(NN + 63) / 64, 128>>>(0, W1, b1, g1, be1);
    k_gather<<<(NN * 32 + 255) / 256, 256>>>(h1h);
    k_gemm  <<<(NN + 63) / 64, 128>>>(1, W2, b2, g2, be2);

    k_poolcls<<<NG, 512>>>(gid, Wc1, bc1, g3, be3, Wc2, bc2, g4, be4, Wc3, bc3, out);
}

// round 17
// speedup vs baseline: 1.8782x; 1.0449x over previous
#include <cuda_runtime.h>
#include <cuda_fp16.h>
#include <math.h>

#define NN 100000
#define NE 1200000
#define NG 512
#define MAXD 64

// -------- scratch (device globals; no allocation) --------
// Feature arrays have NN+1 rows: row NN is an all-zero dummy for padded edges.
// Device globals are zero-initialized at module load; the dummy rows are NEVER
// written by any kernel, so they stay zero across all replays. g_dego/g_degi
// are re-zeroed at the tail of k_poolcls so every kernel_launch call starts
// from identical state (first call uses the load-time zeros).
static __device__ __half2  g_xh  [(NN + 1) * 32];
static __device__ __half2  g_h1h [(NN + 1) * 32];
static __device__ unsigned g_aggh[NN * 32];  // gather output (fp16 half2 pairs)
static __device__ float    g_h2  [NN * 64];  // conv2 output (fp32, for pooling)
static __device__ int      g_dego[NN];
static __device__ int      g_degi[NN];
static __device__ int      g_ebuf[NN * MAXD];

// -------- fused degrees + bucket fill --------
__global__ void k_degfill(const int4* __restrict__ src4, const int4* __restrict__ dst4) {
    int i = blockIdx.x * blockDim.x + threadIdx.x;
    if (i < NE / 4) {
        int4 s = __ldg(&src4[i]);
        int4 d = __ldg(&dst4[i]);
        atomicAdd(&g_dego[s.x], 1); atomicAdd(&g_dego[s.y], 1);
        atomicAdd(&g_dego[s.z], 1); atomicAdd(&g_dego[s.w], 1);
        int p0 = atomicAdd(&g_degi[d.x], 1); g_ebuf[d.x * MAXD + p0] = s.x;
        int p1 = atomicAdd(&g_degi[d.y], 1); g_ebuf[d.y * MAXD + p1] = s.y;
        int p2 = atomicAdd(&g_degi[d.z], 1); g_ebuf[d.z * MAXD + p2] = s.z;
        int p3 = atomicAdd(&g_degi[d.w], 1); g_ebuf[d.w * MAXD + p3] = s.w;
    }
}

// -------- prep: g_xh = half(x * ns); pad buckets to ceil8(deg) with dummy NN --------
__global__ void k_prep(const float* __restrict__ x) {
    int i = blockIdx.x * blockDim.x + threadIdx.x;
    if (i < NN * 16) {
        float4 v = __ldg(&((const float4*)x)[i]);
        int dov = __ldg(&g_dego[i >> 4]); if (dov < 1) dov = 1;
        float s = rsqrtf((float)dov);
        g_xh[i * 2]     = __floats2half2_rn(v.x * s, v.y * s);
        g_xh[i * 2 + 1] = __floats2half2_rn(v.z * s, v.w * s);
    }
    if (i < NN) {
        int deg = __ldg(&g_degi[i]);
        int padded = (deg + 7) & ~7;
        for (int e = deg; e < padded; e++) g_ebuf[i * MAXD + e] = NN;
    }
}

#define H2REF(x) (*reinterpret_cast<const __half2*>(&(x)))

// -------- gather: 1 warp/node; 8-edge chunks, unpredicated loads --------
// Common path (deg<=32): single index register, no select, no second prefetch.
__global__ void __launch_bounds__(256) k_gather(const uint2* __restrict__ xin) {
    int gw = (blockIdx.x * blockDim.x + threadIdx.x) >> 5;
    if (gw >= NN) return;
    int lane = threadIdx.x & 31;
    int hf   = lane >> 4;
    int l16  = lane & 15;

    int deg = __ldg(&g_degi[gw]);
    const int* bucket = &g_ebuf[gw * MAXD];
    int sidx0 = __ldg(&bucket[lane]);

    float ax0 = 0.f, ay0 = 0.f, ax1 = 0.f, ay1 = 0.f;

    if (deg <= 32) {
        #pragma unroll 1
        for (int e0 = 0; e0 < deg; e0 += 8) {
            int sA = __shfl_sync(0xffffffffu, sidx0, e0 + hf);
            int sB = __shfl_sync(0xffffffffu, sidx0, e0 + 2 + hf);
            int sC = __shfl_sync(0xffffffffu, sidx0, e0 + 4 + hf);
            int sD = __shfl_sync(0xffffffffu, sidx0, e0 + 6 + hf);
            uint2 uA = __ldg(&xin[sA * 16 + l16]);
            uint2 uB = __ldg(&xin[sB * 16 + l16]);
            uint2 uC = __ldg(&xin[sC * 16 + l16]);
            uint2 uD = __ldg(&xin[sD * 16 + l16]);
            __half2 t0 = __hadd2(__hadd2(H2REF(uA.x), H2REF(uB.x)),
                                 __hadd2(H2REF(uC.x), H2REF(uD.x)));
            __half2 t1 = __hadd2(__hadd2(H2REF(uA.y), H2REF(uB.y)),
                                 __hadd2(H2REF(uC.y), H2REF(uD.y)));
            float2 f0 = __half22float2(t0);
            float2 f1 = __half22float2(t1);
            ax0 += f0.x; ay0 += f0.y;
            ax1 += f1.x; ay1 += f1.y;
        }
    } else {
        int sidx1 = __ldg(&bucket[32 + lane]);
        #pragma unroll 1
        for (int e0 = 0; e0 < deg; e0 += 8) {
            int sv = (e0 < 32) ? sidx0 : sidx1;
            int sA = __shfl_sync(0xffffffffu, sv, e0 + hf);
            int sB = __shfl_sync(0xffffffffu, sv, e0 + 2 + hf);
            int sC = __shfl_sync(0xffffffffu, sv, e0 + 4 + hf);
            int sD = __shfl_sync(0xffffffffu, sv, e0 + 6 + hf);
            uint2 uA = __ldg(&xin[sA * 16 + l16]);
            uint2 uB = __ldg(&xin[sB * 16 + l16]);
            uint2 uC = __ldg(&xin[sC * 16 + l16]);
            uint2 uD = __ldg(&xin[sD * 16 + l16]);
            __half2 t0 = __hadd2(__hadd2(H2REF(uA.x), H2REF(uB.x)),
                                 __hadd2(H2REF(uC.x), H2REF(uD.x)));
            __half2 t1 = __hadd2(__hadd2(H2REF(uA.y), H2REF(uB.y)),
                                 __hadd2(H2REF(uC.y), H2REF(uD.y)));
            float2 f0 = __half22float2(t0);
            float2 f1 = __half22float2(t1);
            ax0 += f0.x; ay0 += f0.y;
            ax1 += f1.x; ay1 += f1.y;
        }
    }

    ax0 += __shfl_xor_sync(0xffffffffu, ax0, 16);
    ay0 += __shfl_xor_sync(0xffffffffu, ay0, 16);
    ax1 += __shfl_xor_sync(0xffffffffu, ax1, 16);
    ay1 += __shfl_xor_sync(0xffffffffu, ay1, 16);

    if (hf == 0) {
        int div_ = deg; if (div_ < 1) div_ = 1;
        float ndv = rsqrtf((float)div_);
        __half2 h0 = __floats2half2_rn(ax0 * ndv, ay0 * ndv);
        __half2 h1 = __floats2half2_rn(ax1 * ndv, ay1 * ndv);
        ((uint2*)g_aggh)[gw * 16 + l16] =
            make_uint2(*reinterpret_cast<unsigned*>(&h0), *reinterpret_cast<unsigned*>(&h1));
    }
}

// -------- tensor-core GEMM (round-15 proven): mma m16n8k16, fused LN/ReLU --------
#define XP 72

__device__ __forceinline__ void ldsm_x4(unsigned& r0, unsigned& r1, unsigned& r2, unsigned& r3, unsigned addr) {
    asm volatile("ldmatrix.sync.aligned.m8n8.x4.shared.b16 {%0,%1,%2,%3}, [%4];"
                 : "=r"(r0), "=r"(r1), "=r"(r2), "=r"(r3) : "r"(addr));
}
__device__ __forceinline__ void ldsm_x2t(unsigned& r0, unsigned& r1, unsigned addr) {
    asm volatile("ldmatrix.sync.aligned.m8n8.x2.trans.shared.b16 {%0,%1}, [%2];"
                 : "=r"(r0), "=r"(r1) : "r"(addr));
}
__device__ __forceinline__ void mma16816(float* c, const unsigned* a, const unsigned* bf) {
    asm volatile("mma.sync.aligned.m16n8k16.row.col.f32.f16.f16.f32 "
                 "{%0,%1,%2,%3},{%4,%5,%6,%7},{%8,%9},{%0,%1,%2,%3};"
                 : "+f"(c[0]), "+f"(c[1]), "+f"(c[2]), "+f"(c[3])
                 : "r"(a[0]), "r"(a[1]), "r"(a[2]), "r"(a[3]), "r"(bf[0]), "r"(bf[1]));
}

__global__ void __launch_bounds__(128) k_gemm(
        int last,
        const float* __restrict__ W, const float* __restrict__ b,
        const float* __restrict__ gm, const float* __restrict__ bt) {
    __shared__ __align__(16) __half Xh[64 * XP];
    __shared__ __align__(16) __half Wh[64 * XP];
    __shared__ float bs[64], gms[64], bts[64];

    int tid = threadIdx.x;
    int base = blockIdx.x * 64;

    const float4* W4 = (const float4*)W;
    #pragma unroll
    for (int i = 0; i < 8; i++) {
        int idx = tid + i * 128;
        float4 w = __ldg(&W4[idx]);
        int k  = idx >> 4;
        int c0 = (idx & 15) * 4;
        __half2* dst = (__half2*)&Wh[k * XP + c0];
        dst[0] = __floats2half2_rn(w.x, w.y);
        dst[1] = __floats2half2_rn(w.z, w.w);
    }
    if (tid < 64) { bs[tid] = b[tid]; gms[tid] = gm[tid]; bts[tid] = bt[tid]; }

    const uint4* ag = (const uint4*)g_aggh;
    #pragma unroll
    for (int i = 0; i < 4; i++) {
        int idx = tid + i * 128;
        int row = idx >> 3;
        int cu  = idx & 7;
        int grow = base + row;
        uint4 v = (grow < NN) ? __ldg(&ag[grow * 8 + cu]) : make_uint4(0u, 0u, 0u, 0u);
        *(uint4*)&Xh[row * XP + cu * 8] = v;
    }
    __syncthreads();

    int w    = tid >> 5;
    int lane = tid & 31;
    int g    = lane >> 2;
    int tig  = lane & 3;

    float c[8][4];
    #pragma unroll
    for (int nt = 0; nt < 8; nt++)
        #pragma unroll
        for (int j = 0; j < 4; j++) c[nt][j] = 0.f;

    unsigned xbase = (unsigned)__cvta_generic_to_shared(Xh);
    unsigned wbase = (unsigned)__cvta_generic_to_shared(Wh);

    #pragma unroll
    for (int ks = 0; ks < 4; ks++) {
        unsigned a[4];
        unsigned aaddr = xbase +
            (((w * 16 + (lane & 15)) * XP + ks * 16 + (lane >> 4) * 8) << 1);
        ldsm_x4(a[0], a[1], a[2], a[3], aaddr);
        #pragma unroll
        for (int nt = 0; nt < 8; nt++) {
            unsigned bf[2];
            unsigned baddr = wbase + (((ks * 16 + (lane & 15)) * XP + nt * 8) << 1);
            ldsm_x2t(bf[0], bf[1], baddr);
            mma16816(c[nt], a, bf);
        }
    }

    #pragma unroll
    for (int nt = 0; nt < 8; nt++) {
        float b0 = bs[nt * 8 + 2 * tig];
        float b1 = bs[nt * 8 + 2 * tig + 1];
        c[nt][0] += b0; c[nt][1] += b1;
        c[nt][2] += b0; c[nt][3] += b1;
    }

    float sA = 0.f, sB = 0.f;
    #pragma unroll
    for (int nt = 0; nt < 8; nt++) { sA += c[nt][0] + c[nt][1]; sB += c[nt][2] + c[nt][3]; }
    sA += __shfl_xor_sync(0xffffffffu, sA, 1); sA += __shfl_xor_sync(0xffffffffu, sA, 2);
    sB += __shfl_xor_sync(0xffffffffu, sB, 1); sB += __shfl_xor_sync(0xffffffffu, sB, 2);
    float mA = sA * (1.f / 64.f), mB = sB * (1.f / 64.f);

    float vA = 0.f, vB = 0.f;
    #pragma unroll
    for (int nt = 0; nt < 8; nt++) {
        float d;
        d = c[nt][0] - mA; vA += d * d;
        d = c[nt][1] - mA; vA += d * d;
        d = c[nt][2] - mB; vB += d * d;
        d = c[nt][3] - mB; vB += d * d;
    }
    vA += __shfl_xor_sync(0xffffffffu, vA, 1); vA += __shfl_xor_sync(0xffffffffu, vA, 2);
    vB += __shfl_xor_sync(0xffffffffu, vB, 1); vB += __shfl_xor_sync(0xffffffffu, vB, 2);
    float iA = rsqrtf(vA * (1.f / 64.f) + 1e-5f);
    float iB = rsqrtf(vB * (1.f / 64.f) + 1e-5f);

    int rowA = base + w * 16 + g;
    int rowB = rowA + 8;

    if (last) {
        #pragma unroll
        for (int nt = 0; nt < 8; nt++) {
            int col = nt * 8 + 2 * tig;
            float gm0 = gms[col], gm1 = gms[col + 1];
            float bt0 = bts[col], bt1 = bts[col + 1];
            if (rowA < NN) {
                float y0 = fmaxf((c[nt][0] - mA) * iA * gm0 + bt0, 0.f);
                float y1 = fmaxf((c[nt][1] - mA) * iA * gm1 + bt1, 0.f);
                *(float2*)&g_h2[rowA * 64 + col] = make_float2(y0, y1);
            }
            if (rowB < NN) {
                float y2 = fmaxf((c[nt][2] - mB) * iB * gm0 + bt0, 0.f);
                float y3 = fmaxf((c[nt][3] - mB) * iB * gm1 + bt1, 0.f);
                *(float2*)&g_h2[rowB * 64 + col] = make_float2(y2, y3);
            }
        }
    } else {
        float nsA = 0.f, nsB = 0.f;
        if (rowA < NN) { int dv = __ldg(&g_dego[rowA]); if (dv < 1) dv = 1; nsA = rsqrtf((float)dv); }
        if (rowB < NN) { int dv = __ldg(&g_dego[rowB]); if (dv < 1) dv = 1; nsB = rsqrtf((float)dv); }
        #pragma unroll
        for (int nt = 0; nt < 8; nt++) {
            int col = nt * 8 + 2 * tig;
            float gm0 = gms[col], gm1 = gms[col + 1];
            float bt0 = bts[col], bt1 = bts[col + 1];
            if (rowA < NN) {
                float y0 = fmaxf((c[nt][0] - mA) * iA * gm0 + bt0, 0.f);
                float y1 = fmaxf((c[nt][1] - mA) * iA * gm1 + bt1, 0.f);
                g_h1h[rowA * 32 + nt * 4 + tig] = __floats2half2_rn(y0 * nsA, y1 * nsA);
            }
            if (rowB < NN) {
                float y2 = fmaxf((c[nt][2] - mB) * iB * gm0 + bt0, 0.f);
                float y3 = fmaxf((c[nt][3] - mB) * iB * gm1 + bt1, 0.f);
                g_h1h[rowB * 32 + nt * 4 + tig] = __floats2half2_rn(y2 * nsB, y3 * nsB);
            }
        }
    }
}

// -------- fused pooling + classifier head + state re-zero: 512 thr/graph --------
__global__ void __launch_bounds__(512) k_poolcls(
        const int* __restrict__ gid,
        const float* __restrict__ Wc1, const float* __restrict__ bc1,
        const float* __restrict__ g3,  const float* __restrict__ be3,
        const float* __restrict__ Wc2, const float* __restrict__ bc2,
        const float* __restrict__ g4,  const float* __restrict__ be4,
        const float* __restrict__ Wc3, const float* __restrict__ bc3,
        float* __restrict__ out) {
    __shared__ float ss[512], mm[512];
    __shared__ float hA[64], hB[64], o1s[64], red[64];
    int g = blockIdx.x, t = threadIdx.x;
    int col = t & 63, chunk = t >> 6;   // 8 chunks

    // re-zero degree arrays for the next replay (globals start zeroed at load;
    // no kernel in this launch reads them after this point)
    int zi = g * 512 + t;
    if (zi < NN) { g_dego[zi] = 0; g_degi[zi] = 0; }

    int lo = 0, hi = NN;
    while (lo < hi) { int mid = (lo + hi) >> 1; if (__ldg(&gid[mid]) < g)     lo = mid + 1; else hi = mid; }
    int start = lo;
    lo = start; hi = NN;
    while (lo < hi) { int mid = (lo + hi) >> 1; if (__ldg(&gid[mid]) < g + 1) lo = mid + 1; else hi = mid; }
    int end = lo;

    float s = 0.f, m = 0.f;   // post-ReLU >= 0
    for (int n = start + chunk; n < end; n += 8) {
        float v = g_h2[n * 64 + col];
        s += v;
        m = fmaxf(m, v);
    }
    ss[t] = s; mm[t] = m;
    __syncthreads();

    float mv = 0.f, xv = 0.f;
    if (t < 64) {
        float cnt = (float)(end - start); if (cnt < 1.f) cnt = 1.f;
        float su = 0.f, mx = 0.f;
        #pragma unroll
        for (int c8 = 0; c8 < 8; c8++) {
            su += ss[c8 * 64 + t];
            mx = fmaxf(mx, mm[c8 * 64 + t]);
        }
        mv = su / cnt;
        xv = mx;
    }

    if (t < 64) red[t] = mv * mv;
    __syncthreads();
    for (int o = 32; o; o >>= 1) { if (t < o) red[t] += red[t + o]; __syncthreads(); }
    float nA = fmaxf(sqrtf(red[0]), 1e-12f); __syncthreads();
    if (t < 64) red[t] = xv * xv;
    __syncthreads();
    for (int o = 32; o; o >>= 1) { if (t < o) red[t] += red[t + o]; __syncthreads(); }
    float nB = fmaxf(sqrtf(red[0]), 1e-12f); __syncthreads();

    if (t < 64) { hA[t] = mv / nA; hB[t] = xv / nB; }
    __syncthreads();

    float acc = 0.f;
    if (t < 64) {
        acc = bc1[t];
        #pragma unroll 4
        for (int k = 0; k < 64; k++) acc += hA[k] * Wc1[k * 64 + t];
        #pragma unroll 4
        for (int k = 0; k < 64; k++) acc += hB[k] * Wc1[(64 + k) * 64 + t];
        red[t] = acc;
    }
    __syncthreads();
    for (int o = 32; o; o >>= 1) { if (t < o) red[t] += red[t + o]; __syncthreads(); }
    float mean = red[0] * (1.f / 64.f); __syncthreads();
    float dv = acc - mean;
    if (t < 64) red[t] = dv * dv;
    __syncthreads();
    for (int o = 32; o; o >>= 1) { if (t < o) red[t] += red[t + o]; __syncthreads(); }
    float inv = rsqrtf(red[0] * (1.f / 64.f) + 1e-5f); __syncthreads();
    if (t < 64) o1s[t] = fmaxf(dv * inv * g3[t] + be3[t], 0.f);
    __syncthreads();

    if (t < 64) {
        acc = bc2[t];
        #pragma unroll 4
        for (int k = 0; k < 64; k++) acc += o1s[k] * Wc2[k * 64 + t];
        red[t] = acc;
    }
    __syncthreads();
    for (int o = 32; o; o >>= 1) { if (t < o) red[t] += red[t + o]; __syncthreads(); }
    mean = red[0] * (1.f / 64.f); __syncthreads();
    dv = acc - mean;
    if (t < 64) red[t] = dv * dv;
    __syncthreads();
    for (int o = 32; o; o >>= 1) { if (t < o) red[t] += red[t + o]; __syncthreads(); }
    inv = rsqrtf(red[0] * (1.f / 64.f) + 1e-5f); __syncthreads();
    float o2 = fmaxf(dv * inv * g4[t < 64 ? t : 0] + be4[t < 64 ? t : 0], 0.f);

    if (t < 64) red[t] = o2 * Wc3[t];
    __syncthreads();
    for (int o = 32; o; o >>= 1) { if (t < o) red[t] += red[t + o]; __syncthreads(); }
    if (t == 0) out[g] = red[0] + bc3[0];
}

extern "C" void kernel_launch(void* const* d_in, const int* in_sizes, int n_in,
                              void* d_out, int out_size) {
    const float* h   = (const float*)d_in[0];
    const int*   src = (const int*)  d_in[1];
    const int*   dst = (const int*)  d_in[2];
    const int*   gid = (const int*)  d_in[3];
    const float* W1  = (const float*)d_in[4];
    const float* b1  = (const float*)d_in[5];
    const float* W2  = (const float*)d_in[6];
    const float* b2  = (const float*)d_in[7];
    const float* g1  = (const float*)d_in[8];
    const float* be1 = (const float*)d_in[9];
    const float* g2  = (const float*)d_in[10];
    const float* be2 = (const float*)d_in[11];
    const float* g3  = (const float*)d_in[12];
    const float* be3 = (const float*)d_in[13];
    const float* g4  = (const float*)d_in[14];
    const float* be4 = (const float*)d_in[15];
    const float* Wc1 = (const float*)d_in[16];
    const float* bc1 = (const float*)d_in[17];
    const float* Wc2 = (const float*)d_in[18];
    const float* bc2 = (const float*)d_in[19];
    const float* Wc3 = (const float*)d_in[20];
    const float* bc3 = (const float*)d_in[21];
    float* out = (float*)d_out;

    uint2* xh = nullptr; uint2* h1h = nullptr;
    cudaGetSymbolAddress((void**)&xh,  g_xh);
    cudaGetSymbolAddress((void**)&h1h, g_h1h);

    k_degfill<<<(NE / 4 + 255) / 256, 256>>>((const int4*)src, (const int4*)dst);
    k_prep   <<<(NN * 16 + 255) / 256, 256>>>(h);

    k_gather<<<(NN * 32 + 255) / 256, 256>>>(xh);
    k_gemm  <<<(NN + 63) / 64, 128>>>(0, W1, b1, g1, be1);
    k_gather<<<(NN * 32 + 255) / 256, 256>>>(h1h);
    k_gemm  <<<(NN + 63) / 64, 128>>>(1, W2, b2, g2, be2);

    k_poolcls<<<NG, 512>>>(gid, Wc1, bc1, g3, be3, Wc2, bc2, g4, be4, Wc3, bc3, out);
}